// round 2
// baseline (speedup 1.0000x reference)
#include <cuda_runtime.h>
#include <cuda_bf16.h>
#include <cstdint>

// Problem constants (fixed shapes per reference)
#define NB   8
#define LQ   2048
#define CC   256
#define MM   8
#define LL   4
#define PP   4
#define DH   32
#define SS   3840
#define ROWS_Q (NB * LQ)     // 16384
#define ROWS_V (NB * SS)     // 30720
#define MLP  (MM * LL * PP)  // 128

__constant__ int c_lens[4]  = {2048, 1024, 512, 256};
__constant__ int c_start[4] = {0, 2048, 3072, 3584};

// Scratch (device globals; no allocation allowed)
__device__ float g_val[ROWS_V * CC];       // value projection  (~31.5 MB)
__device__ float g_off[ROWS_Q * MLP];      // offset projection (8 MB)
__device__ float g_attnraw[ROWS_Q * MLP];  // attn logits       (8 MB)
__device__ float g_mid[ROWS_Q * CC];       // deform output pre W_out (16.8 MB)

// ---------------------------------------------------------------------------
// 128x128 tiled SGEMM with fused bias: C[Mr,Nc] = A[Mr,K] @ B[K,Nc] + bias[Nc]
// Requires Mr%128==0, Nc%128==0, K%8==0. 256 threads, 8x8 micro-tile.
// ---------------------------------------------------------------------------
__global__ __launch_bounds__(256, 2)
void sgemm128(const float* __restrict__ A, const float* __restrict__ B,
              const float* __restrict__ bias, float* __restrict__ Cmat,
              int Mr, int Nc, int K)
{
    __shared__ float As[8][132];   // padded row: 132*4=528B (16B aligned)
    __shared__ float Bs[8][128];

    const int tid = threadIdx.x;
    const int tx = tid & 15;
    const int ty = tid >> 4;
    const int r0 = blockIdx.y * 128;
    const int c0 = blockIdx.x * 128;

    const int arow = tid >> 1;          // 0..127
    const int akq  = (tid & 1) * 4;     // 0 or 4
    const int bk   = tid >> 5;          // 0..7
    const int bc   = (tid & 31) * 4;    // 0..124

    float acc[8][8];
#pragma unroll
    for (int i = 0; i < 8; ++i)
#pragma unroll
        for (int j = 0; j < 8; ++j) acc[i][j] = 0.f;

    for (int k0 = 0; k0 < K; k0 += 8) {
        float4 av = *reinterpret_cast<const float4*>(
            &A[(size_t)(r0 + arow) * K + k0 + akq]);
        As[akq + 0][arow] = av.x;
        As[akq + 1][arow] = av.y;
        As[akq + 2][arow] = av.z;
        As[akq + 3][arow] = av.w;
        float4 bv = *reinterpret_cast<const float4*>(
            &B[(size_t)(k0 + bk) * Nc + c0 + bc]);
        *reinterpret_cast<float4*>(&Bs[bk][bc]) = bv;
        __syncthreads();

#pragma unroll
        for (int k = 0; k < 8; ++k) {
            float a[8], b[8];
            *(float4*)&a[0] = *(const float4*)&As[k][ty * 8];
            *(float4*)&a[4] = *(const float4*)&As[k][ty * 8 + 4];
            *(float4*)&b[0] = *(const float4*)&Bs[k][tx * 8];
            *(float4*)&b[4] = *(const float4*)&Bs[k][tx * 8 + 4];
#pragma unroll
            for (int i = 0; i < 8; ++i)
#pragma unroll
                for (int j = 0; j < 8; ++j)
                    acc[i][j] += a[i] * b[j];
        }
        __syncthreads();
    }

    // epilogue + bias
    float bsv[8];
#pragma unroll
    for (int j = 0; j < 8; ++j) bsv[j] = bias[c0 + tx * 8 + j];
#pragma unroll
    for (int i = 0; i < 8; ++i) {
        const int row = r0 + ty * 8 + i;
        float4 o0, o1;
        o0.x = acc[i][0] + bsv[0]; o0.y = acc[i][1] + bsv[1];
        o0.z = acc[i][2] + bsv[2]; o0.w = acc[i][3] + bsv[3];
        o1.x = acc[i][4] + bsv[4]; o1.y = acc[i][5] + bsv[5];
        o1.z = acc[i][6] + bsv[6]; o1.w = acc[i][7] + bsv[7];
        *reinterpret_cast<float4*>(&Cmat[(size_t)row * Nc + c0 + tx * 8])     = o0;
        *reinterpret_cast<float4*>(&Cmat[(size_t)row * Nc + c0 + tx * 8 + 4]) = o1;
    }
}

// ---------------------------------------------------------------------------
// Softmax over L*P=16 per (row, m) + loc computation.
// One block per query row (n*LQ+q); 128 threads -> t = m*16 + (l*4+p).
// Writes attn and loc directly into the output buffer regions.
// ---------------------------------------------------------------------------
__global__ void softmax_loc_kernel(const float* __restrict__ off_raw,
                                   const float* __restrict__ attn_raw,
                                   const float* __restrict__ ref_pts,
                                   float* __restrict__ loc_out,
                                   float* __restrict__ attn_out)
{
    const int row = blockIdx.x;          // 0..16383
    const int t = threadIdx.x;           // 0..127
    const int idx = row * MLP + t;

    float x = attn_raw[idx];
    float mx = x;
#pragma unroll
    for (int o = 8; o >= 1; o >>= 1)
        mx = fmaxf(mx, __shfl_xor_sync(0xffffffffu, mx, o));
    float e = __expf(x - mx);
    float s = e;
#pragma unroll
    for (int o = 8; o >= 1; o >>= 1)
        s += __shfl_xor_sync(0xffffffffu, s, o);
    attn_out[idx] = e / s;

    const int l = (t & 15) >> 2;
    const float Tf = (float)c_lens[l];
    const float ref = ref_pts[row * LL + l];
    loc_out[idx] = ref + off_raw[idx] / Tf;
}

// ---------------------------------------------------------------------------
// Deformable sampling: one warp per (query row, head m); lane = channel d.
// ---------------------------------------------------------------------------
__global__ __launch_bounds__(256)
void deform_sample_kernel(const float* __restrict__ val,
                          const float* __restrict__ loc,
                          const float* __restrict__ attn,
                          float* __restrict__ mid)
{
    const int wid = threadIdx.x >> 5;
    const int lane = threadIdx.x & 31;
    const long long gw = (long long)blockIdx.x * 8 + wid; // 0..131071
    const int m = (int)(gw & 7);
    const int row = (int)(gw >> 3);      // n*LQ + q
    const int n = row >> 11;             // LQ = 2048

    const float* vbase = val + ((size_t)n * SS) * CC + m * DH + lane;
    const int abase = row * MLP + m * 16;

    float acc = 0.f;
#pragma unroll
    for (int i = 0; i < 16; ++i) {
        const int l = i >> 2;
        const int T = c_lens[l];
        const int st = c_start[l];
        const float lc = __ldg(&loc[abase + i]);
        const float aw = __ldg(&attn[abase + i]);
        const float pos = lc * (float)T - 0.5f;
        const float x0f = floorf(pos);
        const float fr = pos - x0f;
        const int x0 = (int)x0f;

        const float w0 = (x0 >= 0 && x0 < T) ? (1.f - fr) * aw : 0.f;
        const float w1 = (x0 + 1 >= 0 && x0 + 1 < T) ? fr * aw : 0.f;
        const int i0 = min(max(x0, 0), T - 1);
        const int i1 = min(max(x0 + 1, 0), T - 1);
        if (w0 != 0.f) acc += w0 * vbase[(size_t)(st + i0) * CC];
        if (w1 != 0.f) acc += w1 * vbase[(size_t)(st + i1) * CC];
    }
    mid[(size_t)row * CC + m * DH + lane] = acc;
}

// ---------------------------------------------------------------------------
extern "C" void kernel_launch(void* const* d_in, const int* in_sizes, int n_in,
                              void* d_out, int out_size)
{
    const float* query   = (const float*)d_in[0];   // (N, LQ, C)
    const float* refpts  = (const float*)d_in[1];   // (N, LQ, L, 1)
    const float* in_flat = (const float*)d_in[2];   // (N, S, C)
    // d_in[3], d_in[4]: temporal_lens / level_start_index (int64) — statically known
    const float* W_off   = (const float*)d_in[5];   // (C, MLP)
    const float* b_off   = (const float*)d_in[6];
    const float* W_attn  = (const float*)d_in[7];
    const float* b_attn  = (const float*)d_in[8];
    const float* W_val   = (const float*)d_in[9];   // (C, C)
    const float* b_val   = (const float*)d_in[10];
    const float* W_out   = (const float*)d_in[11];  // (C, C)
    const float* b_out   = (const float*)d_in[12];

    float* out_main = (float*)d_out;                         // (N,LQ,C)
    float* out_loc  = out_main + (size_t)ROWS_Q * CC;        // (N,LQ,M,L,P)
    float* out_attn = out_loc  + (size_t)ROWS_Q * MLP;       // (N,LQ,M,L,P)

    float *d_val, *d_off, *d_attnraw, *d_mid;
    cudaGetSymbolAddress((void**)&d_val,     g_val);
    cudaGetSymbolAddress((void**)&d_off,     g_off);
    cudaGetSymbolAddress((void**)&d_attnraw, g_attnraw);
    cudaGetSymbolAddress((void**)&d_mid,     g_mid);

    // 1) value projection: (30720 x 256) @ (256 x 256)
    {
        dim3 grid(CC / 128, ROWS_V / 128);
        sgemm128<<<grid, 256>>>(in_flat, W_val, b_val, d_val, ROWS_V, CC, CC);
    }
    // 2) offset projection: (16384 x 256) @ (256 x 128)
    {
        dim3 grid(MLP / 128, ROWS_Q / 128);
        sgemm128<<<grid, 256>>>(query, W_off, b_off, d_off, ROWS_Q, MLP, CC);
    }
    // 3) attn logits: (16384 x 256) @ (256 x 128)
    {
        dim3 grid(MLP / 128, ROWS_Q / 128);
        sgemm128<<<grid, 256>>>(query, W_attn, b_attn, d_attnraw, ROWS_Q, MLP, CC);
    }
    // 4) softmax + loc (writes loc/attn output regions)
    softmax_loc_kernel<<<ROWS_Q, 128>>>(d_off, d_attnraw, refpts, out_loc, out_attn);
    // 5) deformable sampling
    deform_sample_kernel<<<ROWS_Q, 256>>>(d_val, out_loc, out_attn, d_mid);
    // 6) output projection: (16384 x 256) @ (256 x 256) -> out_main
    {
        dim3 grid(CC / 128, ROWS_Q / 128);
        sgemm128<<<grid, 256>>>(d_mid, W_out, b_out, out_main, ROWS_Q, CC, CC);
    }
}

// round 4
// speedup vs baseline: 1.2513x; 1.2513x over previous
#include <cuda_runtime.h>
#include <cuda_bf16.h>
#include <cstdint>

// Problem constants (fixed shapes per reference)
#define NB   8
#define LQ   2048
#define CC   256
#define MM   8
#define LL   4
#define PP   4
#define DH   32
#define SS   3840
#define ROWS_Q (NB * LQ)     // 16384
#define ROWS_V (NB * SS)     // 30720
#define MLP  (MM * LL * PP)  // 128

__constant__ int c_lens[4]  = {2048, 1024, 512, 256};
__constant__ int c_start[4] = {0, 2048, 3072, 3584};

// Scratch (device globals; no allocation allowed)
__device__ float g_val[ROWS_V * CC];       // value projection  (~31.5 MB)
__device__ float g_off[ROWS_Q * MLP];      // offset projection (8 MB)
__device__ float g_attnraw[ROWS_Q * MLP];  // attn logits       (8 MB)
__device__ float g_mid[ROWS_Q * CC];       // deform output pre W_out (16.8 MB)

// ---------------------------------------------------------------------------
// helpers
// ---------------------------------------------------------------------------
static __device__ __forceinline__ uint32_t smem_u32(const void* p) {
    uint32_t a;
    asm("{ .reg .u64 t; cvta.to.shared.u64 t, %1; cvt.u32.u64 %0, t; }"
        : "=r"(a) : "l"(p));
    return a;
}
static __device__ __forceinline__ uint32_t swz128(uint32_t off) {
    return off ^ ((off >> 3) & 0x70);
}
static __device__ __forceinline__ uint32_t pack_hi(float a, float b,
                                                   float& la, float& lb) {
    __nv_bfloat16 ha = __float2bfloat16(a);
    __nv_bfloat16 hb = __float2bfloat16(b);
    la = a - __bfloat162float(ha);
    lb = b - __bfloat162float(hb);
    return (uint32_t)__bfloat16_as_ushort(ha) |
           ((uint32_t)__bfloat16_as_ushort(hb) << 16);
}
static __device__ __forceinline__ uint32_t pack_bf(float a, float b) {
    return (uint32_t)__bfloat16_as_ushort(__float2bfloat16(a)) |
           ((uint32_t)__bfloat16_as_ushort(__float2bfloat16(b)) << 16);
}

#define LDMX4(r0, r1, r2, r3, addr) \
    asm volatile("ldmatrix.sync.aligned.m8n8.x4.shared.b16 {%0,%1,%2,%3}, [%4];" \
                 : "=r"(r0), "=r"(r1), "=r"(r2), "=r"(r3) : "r"(addr))

#define MMA16816(c, a, b0, b1) \
    asm volatile("mma.sync.aligned.m16n8k16.row.col.f32.bf16.bf16.f32 " \
                 "{%0,%1,%2,%3}, {%4,%5,%6,%7}, {%8,%9}, {%0,%1,%2,%3};" \
                 : "+f"((c)[0]), "+f"((c)[1]), "+f"((c)[2]), "+f"((c)[3]) \
                 : "r"((a)[0]), "r"((a)[1]), "r"((a)[2]), "r"((a)[3]), \
                   "r"(b0), "r"(b1))

// ===========================================================================
// Tensor-core GEMM via mma.sync (bf16 hi/lo split, fp32 accumulate):
// C[Mr,Nc] = A[Mr,K] @ B[K,Nc] + bias.
// Tile 128x128, 8 warps (2m x 4n of 64x32 warp tiles), K chunks of 64.
// SW128-swizzled smem, ldmatrix fragment loads.
// Requires Mr%128==0, Nc%128==0, K%64==0.
// ===========================================================================
#define SA_HI   0
#define SA_LO   16384
#define SB_HI   32768
#define SB_LO   49152
#define GEMM_SMEM 65536

__global__ __launch_bounds__(256)
void gemm_bf16(const float* __restrict__ A, const float* __restrict__ B,
               const float* __restrict__ bias, float* __restrict__ Cmat,
               int Mr, int Nc, int K)
{
    extern __shared__ char smem[];
    const uint32_t sb = smem_u32(smem);
    const int tid = threadIdx.x;
    const int lane = tid & 31, wid = tid >> 5;
    const int r0 = blockIdx.y * 128, c0 = blockIdx.x * 128;
    const int wm = (wid >> 2) * 64;       // warp m offset in tile
    const int wn = (wid & 3) * 32;        // warp n offset in tile

    float acc[4][4][4];
#pragma unroll
    for (int mt = 0; mt < 4; ++mt)
#pragma unroll
        for (int j = 0; j < 4; ++j)
#pragma unroll
            for (int r = 0; r < 4; ++r) acc[mt][j][r] = 0.f;

    // ldmatrix lane address bases (byte offsets into a 128x128B tile buffer)
    const int matq = lane >> 3, rq = lane & 7;
    uint32_t aRowB[4], bRowB[2];
#pragma unroll
    for (int mt = 0; mt < 4; ++mt)
        aRowB[mt] = (uint32_t)((wm + mt * 16 + (matq & 1) * 8 + rq) * 128 +
                               (matq >> 1) * 16);
#pragma unroll
    for (int nt = 0; nt < 2; ++nt)
        bRowB[nt] = (uint32_t)((wn + nt * 16 + (matq >> 1) * 8 + rq) * 128 +
                               (matq & 1) * 16);

    const int nchunks = K >> 6;
    for (int ch = 0; ch < nchunks; ++ch) {
        const int k0 = ch << 6;
        // ---- A tile: 128 rows x 64 k fp32 -> bf16 hi/lo, SW128 ----
        for (int i = tid; i < 2048; i += 256) {
            const int idx4 = i * 4;
            const int row = idx4 >> 6;
            const int kk = idx4 & 63;
            const float4 v = *reinterpret_cast<const float4*>(
                &A[(size_t)(r0 + row) * K + k0 + kk]);
            float l0, l1, l2, l3;
            const uint32_t h01 = pack_hi(v.x, v.y, l0, l1);
            const uint32_t h23 = pack_hi(v.z, v.w, l2, l3);
            const uint32_t sw = swz128((uint32_t)(row * 128 + kk * 2));
            *reinterpret_cast<uint2*>(smem + SA_HI + sw) =
                make_uint2(h01, h23);
            *reinterpret_cast<uint2*>(smem + SA_LO + sw) =
                make_uint2(pack_bf(l0, l1), pack_bf(l2, l3));
        }
        // ---- B tile: Bs[n][k] = B[k0+k][c0+n]; 128 n x 64 k ----
        {
            const int n = tid & 127;
            const int kb = (tid >> 7) * 32;
            const float* Bp = B + (size_t)(k0 + kb) * Nc + c0 + n;
#pragma unroll 4
            for (int kp = 0; kp < 16; ++kp) {
                const float b0 = Bp[(size_t)(2 * kp) * Nc];
                const float b1 = Bp[(size_t)(2 * kp + 1) * Nc];
                float l0, l1;
                const uint32_t hp = pack_hi(b0, b1, l0, l1);
                const uint32_t lp = pack_bf(l0, l1);
                const uint32_t sw = swz128((uint32_t)(n * 128 + (kb + 2 * kp) * 2));
                *reinterpret_cast<uint32_t*>(smem + SB_HI + sw) = hp;
                *reinterpret_cast<uint32_t*>(smem + SB_LO + sw) = lp;
            }
        }
        __syncthreads();

#pragma unroll
        for (int ks = 0; ks < 4; ++ks) {
            uint32_t ah[4][4], al[4][4], bh[2][4], bl[2][4];
#pragma unroll
            for (int mt = 0; mt < 4; ++mt) {
                const uint32_t off = swz128(aRowB[mt] + ks * 32);
                LDMX4(ah[mt][0], ah[mt][1], ah[mt][2], ah[mt][3],
                      sb + SA_HI + off);
                LDMX4(al[mt][0], al[mt][1], al[mt][2], al[mt][3],
                      sb + SA_LO + off);
            }
#pragma unroll
            for (int nt = 0; nt < 2; ++nt) {
                const uint32_t off = swz128(bRowB[nt] + ks * 32);
                LDMX4(bh[nt][0], bh[nt][1], bh[nt][2], bh[nt][3],
                      sb + SB_HI + off);
                LDMX4(bl[nt][0], bl[nt][1], bl[nt][2], bl[nt][3],
                      sb + SB_LO + off);
            }
#pragma unroll
            for (int mt = 0; mt < 4; ++mt) {
#pragma unroll
                for (int nt = 0; nt < 2; ++nt) {
#pragma unroll
                    for (int h = 0; h < 2; ++h) {
                        const int j = nt * 2 + h;
                        MMA16816(acc[mt][j], ah[mt], bh[nt][2 * h], bh[nt][2 * h + 1]);
                        MMA16816(acc[mt][j], ah[mt], bl[nt][2 * h], bl[nt][2 * h + 1]);
                        MMA16816(acc[mt][j], al[mt], bh[nt][2 * h], bh[nt][2 * h + 1]);
                    }
                }
            }
        }
        __syncthreads();
    }

    // ---- epilogue: add bias, write C ----
    const int rbase = r0 + wm + (lane >> 2);
    const int cbase = c0 + wn + (lane & 3) * 2;
#pragma unroll
    for (int j = 0; j < 4; ++j) {
        const int col = cbase + j * 8;
        const float bx = __ldg(&bias[col]);
        const float by = __ldg(&bias[col + 1]);
#pragma unroll
        for (int mt = 0; mt < 4; ++mt) {
            const int row = rbase + mt * 16;
            float2 v0 = make_float2(acc[mt][j][0] + bx, acc[mt][j][1] + by);
            float2 v1 = make_float2(acc[mt][j][2] + bx, acc[mt][j][3] + by);
            *reinterpret_cast<float2*>(&Cmat[(size_t)row * Nc + col]) = v0;
            *reinterpret_cast<float2*>(&Cmat[(size_t)(row + 8) * Nc + col]) = v1;
        }
    }
}

// ---------------------------------------------------------------------------
// Softmax over L*P=16 per (row, m) + loc computation.
// ---------------------------------------------------------------------------
__global__ void softmax_loc_kernel(const float* __restrict__ off_raw,
                                   const float* __restrict__ attn_raw,
                                   const float* __restrict__ ref_pts,
                                   float* __restrict__ loc_out,
                                   float* __restrict__ attn_out)
{
    const int row = blockIdx.x;
    const int t = threadIdx.x;
    const int idx = row * MLP + t;

    float x = attn_raw[idx];
    float mx = x;
#pragma unroll
    for (int o = 8; o >= 1; o >>= 1)
        mx = fmaxf(mx, __shfl_xor_sync(0xffffffffu, mx, o));
    float e = __expf(x - mx);
    float s = e;
#pragma unroll
    for (int o = 8; o >= 1; o >>= 1)
        s += __shfl_xor_sync(0xffffffffu, s, o);
    attn_out[idx] = e / s;

    const int l = (t & 15) >> 2;
    const float Tf = (float)c_lens[l];
    const float ref = ref_pts[row * LL + l];
    loc_out[idx] = ref + off_raw[idx] / Tf;
}

// ---------------------------------------------------------------------------
// Deformable sampling: one warp per (query row, head m); lane = channel d.
// ---------------------------------------------------------------------------
__global__ __launch_bounds__(256)
void deform_sample_kernel(const float* __restrict__ val,
                          const float* __restrict__ loc,
                          const float* __restrict__ attn,
                          float* __restrict__ mid)
{
    const int wid = threadIdx.x >> 5;
    const int lane = threadIdx.x & 31;
    const long long gw = (long long)blockIdx.x * 8 + wid;
    const int m = (int)(gw & 7);
    const int row = (int)(gw >> 3);
    const int n = row >> 11;

    const float* vbase = val + ((size_t)n * SS) * CC + m * DH + lane;
    const int abase = row * MLP + m * 16;

    float acc = 0.f;
#pragma unroll
    for (int i = 0; i < 16; ++i) {
        const int l = i >> 2;
        const int T = c_lens[l];
        const int st = c_start[l];
        const float lc = __ldg(&loc[abase + i]);
        const float aw = __ldg(&attn[abase + i]);
        const float pos = lc * (float)T - 0.5f;
        const float x0f = floorf(pos);
        const float fr = pos - x0f;
        const int x0 = (int)x0f;

        const float w0 = (x0 >= 0 && x0 < T) ? (1.f - fr) * aw : 0.f;
        const float w1 = (x0 + 1 >= 0 && x0 + 1 < T) ? fr * aw : 0.f;
        const int i0 = min(max(x0, 0), T - 1);
        const int i1 = min(max(x0 + 1, 0), T - 1);
        if (w0 != 0.f) acc += w0 * vbase[(size_t)(st + i0) * CC];
        if (w1 != 0.f) acc += w1 * vbase[(size_t)(st + i1) * CC];
    }
    mid[(size_t)row * CC + m * DH + lane] = acc;
}

// ---------------------------------------------------------------------------
extern "C" void kernel_launch(void* const* d_in, const int* in_sizes, int n_in,
                              void* d_out, int out_size)
{
    const float* query   = (const float*)d_in[0];
    const float* refpts  = (const float*)d_in[1];
    const float* in_flat = (const float*)d_in[2];
    const float* W_off   = (const float*)d_in[5];
    const float* b_off   = (const float*)d_in[6];
    const float* W_attn  = (const float*)d_in[7];
    const float* b_attn  = (const float*)d_in[8];
    const float* W_val   = (const float*)d_in[9];
    const float* b_val   = (const float*)d_in[10];
    const float* W_out   = (const float*)d_in[11];
    const float* b_out   = (const float*)d_in[12];

    float* out_main = (float*)d_out;
    float* out_loc  = out_main + (size_t)ROWS_Q * CC;
    float* out_attn = out_loc  + (size_t)ROWS_Q * MLP;

    float *d_val, *d_off, *d_attnraw, *d_mid;
    cudaGetSymbolAddress((void**)&d_val,     g_val);
    cudaGetSymbolAddress((void**)&d_off,     g_off);
    cudaGetSymbolAddress((void**)&d_attnraw, g_attnraw);
    cudaGetSymbolAddress((void**)&d_mid,     g_mid);

    static bool attr_set = false;
    if (!attr_set) {
        cudaFuncSetAttribute(gemm_bf16,
                             cudaFuncAttributeMaxDynamicSharedMemorySize,
                             GEMM_SMEM);
        attr_set = true;
    }

    // 1) value projection: (30720 x 256) @ (256 x 256)
    gemm_bf16<<<dim3(CC / 128, ROWS_V / 128), 256, GEMM_SMEM>>>(
        in_flat, W_val, b_val, d_val, ROWS_V, CC, CC);
    // 2) offset projection: (16384 x 256) @ (256 x 128)
    gemm_bf16<<<dim3(1, ROWS_Q / 128), 256, GEMM_SMEM>>>(
        query, W_off, b_off, d_off, ROWS_Q, MLP, CC);
    // 3) attn logits
    gemm_bf16<<<dim3(1, ROWS_Q / 128), 256, GEMM_SMEM>>>(
        query, W_attn, b_attn, d_attnraw, ROWS_Q, MLP, CC);
    // 4) softmax + loc
    softmax_loc_kernel<<<ROWS_Q, 128>>>(d_off, d_attnraw, refpts, out_loc, out_attn);
    // 5) deformable sampling
    deform_sample_kernel<<<ROWS_Q, 256>>>(d_val, out_loc, out_attn, d_mid);
    // 6) output projection -> out_main
    gemm_bf16<<<dim3(CC / 128, ROWS_Q / 128), 256, GEMM_SMEM>>>(
        d_mid, W_out, b_out, out_main, ROWS_Q, CC, CC);
}

// round 8
// speedup vs baseline: 1.9598x; 1.5662x over previous
#include <cuda_runtime.h>
#include <cuda_bf16.h>
#include <cstdint>

// Problem constants (fixed shapes per reference)
#define NB   8
#define LQ   2048
#define CC   256
#define MM   8
#define LL   4
#define PP   4
#define DH   32
#define SS   3840
#define ROWS_Q (NB * LQ)     // 16384
#define ROWS_V (NB * SS)     // 30720
#define MLP  (MM * LL * PP)  // 128

__constant__ int c_lens[4]  = {2048, 1024, 512, 256};
__constant__ int c_start[4] = {0, 2048, 3072, 3584};

// ---------------------------------------------------------------------------
// Scratch (device globals; no allocation allowed)
// ---------------------------------------------------------------------------
__device__ float g_val[ROWS_V * CC];           // value projection (fp32)
__device__ float g_offattn[ROWS_Q * 256];      // [off | attn logits]
__device__ float g_mid[ROWS_Q * CC];           // deform output pre W_out

__device__ __nv_bfloat16 g_in_h[ROWS_V * CC];  // in_flatten hi/lo
__device__ __nv_bfloat16 g_in_l[ROWS_V * CC];
__device__ __nv_bfloat16 g_q_h[ROWS_Q * CC];   // query hi/lo
__device__ __nv_bfloat16 g_q_l[ROWS_Q * CC];
__device__ __nv_bfloat16 g_mid_h[ROWS_Q * CC]; // mid hi/lo
__device__ __nv_bfloat16 g_mid_l[ROWS_Q * CC];

__device__ __nv_bfloat16 g_wv_h[CC * CC],   g_wv_l[CC * CC];    // W_val^T
__device__ __nv_bfloat16 g_wcat_h[CC * CC], g_wcat_l[CC * CC];  // [W_off|W_attn]^T
__device__ __nv_bfloat16 g_wo_h[CC * CC],   g_wo_l[CC * CC];    // W_out^T
__device__ float g_bcat[256];

// ---------------------------------------------------------------------------
// helpers
// ---------------------------------------------------------------------------
static __device__ __forceinline__ uint32_t smem_u32(const void* p) {
    uint32_t a;
    asm("{ .reg .u64 t; cvta.to.shared.u64 t, %1; cvt.u32.u64 %0, t; }"
        : "=r"(a) : "l"(p));
    return a;
}
static __device__ __forceinline__ uint32_t swz128(uint32_t off) {
    return off ^ ((off >> 3) & 0x70);
}
static __device__ __forceinline__ uint32_t pack_hi(float a, float b,
                                                   float& la, float& lb) {
    __nv_bfloat16 ha = __float2bfloat16(a);
    __nv_bfloat16 hb = __float2bfloat16(b);
    la = a - __bfloat162float(ha);
    lb = b - __bfloat162float(hb);
    return (uint32_t)__bfloat16_as_ushort(ha) |
           ((uint32_t)__bfloat16_as_ushort(hb) << 16);
}
static __device__ __forceinline__ uint32_t pack_bf(float a, float b) {
    return (uint32_t)__bfloat16_as_ushort(__float2bfloat16(a)) |
           ((uint32_t)__bfloat16_as_ushort(__float2bfloat16(b)) << 16);
}

#define LDMX4(r0, r1, r2, r3, addr) \
    asm volatile("ldmatrix.sync.aligned.m8n8.x4.shared.b16 {%0,%1,%2,%3}, [%4];" \
                 : "=r"(r0), "=r"(r1), "=r"(r2), "=r"(r3) : "r"(addr))

#define MMA16816(c, a, b0, b1) \
    asm volatile("mma.sync.aligned.m16n8k16.row.col.f32.bf16.bf16.f32 " \
                 "{%0,%1,%2,%3}, {%4,%5,%6,%7}, {%8,%9}, {%0,%1,%2,%3};" \
                 : "+f"((c)[0]), "+f"((c)[1]), "+f"((c)[2]), "+f"((c)[3]) \
                 : "r"((a)[0]), "r"((a)[1]), "r"((a)[2]), "r"((a)[3]), \
                   "r"(b0), "r"(b1))

#define CP16(dst, src) \
    asm volatile("cp.async.cg.shared.global [%0], [%1], 16;" \
                 :: "r"(dst), "l"(src))
#define CP_COMMIT() asm volatile("cp.async.commit_group;" ::: "memory")
#define CP_WAIT(n)  asm volatile("cp.async.wait_group %0;" :: "n"(n) : "memory")

// ===========================================================================
// Conversion kernels
// ===========================================================================
__global__ void convert_act(const float* __restrict__ src,
                            __nv_bfloat16* __restrict__ hi,
                            __nv_bfloat16* __restrict__ lo, int n4)
{
    int i = blockIdx.x * blockDim.x + threadIdx.x;
    const int stride = gridDim.x * blockDim.x;
    for (; i < n4; i += stride) {
        const float4 v = reinterpret_cast<const float4*>(src)[i];
        float l0, l1, l2, l3;
        const uint32_t h01 = pack_hi(v.x, v.y, l0, l1);
        const uint32_t h23 = pack_hi(v.z, v.w, l2, l3);
        reinterpret_cast<uint2*>(hi)[i] = make_uint2(h01, h23);
        reinterpret_cast<uint2*>(lo)[i] = make_uint2(pack_bf(l0, l1),
                                                     pack_bf(l2, l3));
    }
}

// Transpose + convert weight: W (K x N fp32) -> Th/Tl (N x K bf16)
__global__ void convert_wt(const float* __restrict__ W,
                           __nv_bfloat16* __restrict__ Th,
                           __nv_bfloat16* __restrict__ Tl, int K, int N)
{
    __shared__ float s[64][65];
    const int n0 = blockIdx.x * 64, k0 = blockIdx.y * 64;
    const int t = threadIdx.x;
#pragma unroll
    for (int j = 0; j < 16; ++j) {
        const int idx = t + j * 256;
        const int r = idx >> 6, c = idx & 63;
        s[r][c] = W[(size_t)(k0 + r) * N + n0 + c];
    }
    __syncthreads();
#pragma unroll
    for (int j = 0; j < 16; ++j) {
        const int idx = t + j * 256;
        const int r = idx >> 6, c = idx & 63;
        const float v = s[c][r];
        const __nv_bfloat16 h = __float2bfloat16(v);
        const float l = v - __bfloat162float(h);
        Th[(size_t)(n0 + r) * K + k0 + c] = h;
        Tl[(size_t)(n0 + r) * K + k0 + c] = __float2bfloat16(l);
    }
}

__global__ void bias_cat(const float* __restrict__ b_off,
                         const float* __restrict__ b_attn,
                         float* __restrict__ bcat)
{
    const int t = threadIdx.x;
    bcat[t] = (t < 128) ? b_off[t] : b_attn[t - 128];
}

// ===========================================================================
// Pipelined bf16 GEMM (mma.sync, hi/lo split, fp32 accumulate):
// C[Mr,Nc] = A[Mr,K] @ B^T[Nc,K] + bias.   A,B in bf16 hi/lo; K%64==0.
// Tile 128x128, 8 warps (2m x 4n of 64x32), K chunks of 64, 2-stage cp.async.
// ===========================================================================
#define STG_SZ  65536
#define T_AH    0
#define T_AL    16384
#define T_BH    32768
#define T_BL    49152
#define GEMM_SMEM (2 * STG_SZ)

__global__ __launch_bounds__(256)
void gemm_bf16v2(const __nv_bfloat16* __restrict__ Ah,
                 const __nv_bfloat16* __restrict__ Al,
                 const __nv_bfloat16* __restrict__ Bh,
                 const __nv_bfloat16* __restrict__ Bl,
                 const float* __restrict__ bias, float* __restrict__ Cmat,
                 int Mr, int Nc, int K)
{
    extern __shared__ char smem[];
    const uint32_t sb = smem_u32(smem);
    const int tid = threadIdx.x;
    const int lane = tid & 31, wid = tid >> 5;
    const int r0 = blockIdx.y * 128, c0 = blockIdx.x * 128;
    const int wm = (wid >> 2) * 64;
    const int wn = (wid & 3) * 32;

    float acc[4][4][4];
#pragma unroll
    for (int mt = 0; mt < 4; ++mt)
#pragma unroll
        for (int j = 0; j < 4; ++j)
#pragma unroll
            for (int r = 0; r < 4; ++r) acc[mt][j][r] = 0.f;

    // cp.async mapping: 4096 16B segs per chunk, 16 per thread
    // seg: tile = seg>>10 (0:AH 1:AL 2:BH 3:BL), row = (seg&1023)>>3, s8 = seg&7
    const __nv_bfloat16* srcs[4] = {Ah, Al, Bh, Bl};

    auto load_chunk = [&](int k0, uint32_t stgBase) {
#pragma unroll
        for (int j = 0; j < 16; ++j) {
            const int seg = tid + j * 256;
            const int tile = seg >> 10;
            const int row = (seg & 1023) >> 3;
            const int s8 = seg & 7;
            const int grow = (tile < 2) ? (r0 + row) : (c0 + row);
            const __nv_bfloat16* src =
                srcs[tile] + (size_t)grow * K + k0 + s8 * 8;
            const uint32_t dst =
                stgBase + tile * 16384 + swz128((uint32_t)(row * 128 + s8 * 16));
            CP16(dst, src);
        }
        CP_COMMIT();
    };

    // ldmatrix lane address bases (byte offsets within one 128x128B tile)
    const int matq = lane >> 3, rq = lane & 7;
    uint32_t aRowB[4], bRowB[2];
#pragma unroll
    for (int mt = 0; mt < 4; ++mt)
        aRowB[mt] = (uint32_t)((wm + mt * 16 + (matq & 1) * 8 + rq) * 128 +
                               (matq >> 1) * 16);
#pragma unroll
    for (int nt = 0; nt < 2; ++nt)
        bRowB[nt] = (uint32_t)((wn + nt * 16 + (matq >> 1) * 8 + rq) * 128 +
                               (matq & 1) * 16);

    const int nch = K >> 6;
    load_chunk(0, sb);

    for (int ch = 0; ch < nch; ++ch) {
        const uint32_t stg = sb + (uint32_t)(ch & 1) * STG_SZ;
        if (ch + 1 < nch) {
            load_chunk((ch + 1) << 6, sb + (uint32_t)((ch + 1) & 1) * STG_SZ);
            CP_WAIT(1);
        } else {
            CP_WAIT(0);
        }
        __syncthreads();

#pragma unroll
        for (int ks = 0; ks < 4; ++ks) {
            uint32_t ah[4][4], al[4][4], bh[2][4], bl[2][4];
#pragma unroll
            for (int mt = 0; mt < 4; ++mt) {
                const uint32_t off = swz128(aRowB[mt] + ks * 32);
                LDMX4(ah[mt][0], ah[mt][1], ah[mt][2], ah[mt][3],
                      stg + T_AH + off);
                LDMX4(al[mt][0], al[mt][1], al[mt][2], al[mt][3],
                      stg + T_AL + off);
            }
#pragma unroll
            for (int nt = 0; nt < 2; ++nt) {
                const uint32_t off = swz128(bRowB[nt] + ks * 32);
                LDMX4(bh[nt][0], bh[nt][1], bh[nt][2], bh[nt][3],
                      stg + T_BH + off);
                LDMX4(bl[nt][0], bl[nt][1], bl[nt][2], bl[nt][3],
                      stg + T_BL + off);
            }
#pragma unroll
            for (int mt = 0; mt < 4; ++mt) {
#pragma unroll
                for (int nt = 0; nt < 2; ++nt) {
#pragma unroll
                    for (int h = 0; h < 2; ++h) {
                        const int j = nt * 2 + h;
                        MMA16816(acc[mt][j], ah[mt], bh[nt][2 * h], bh[nt][2 * h + 1]);
                        MMA16816(acc[mt][j], ah[mt], bl[nt][2 * h], bl[nt][2 * h + 1]);
                        MMA16816(acc[mt][j], al[mt], bh[nt][2 * h], bh[nt][2 * h + 1]);
                    }
                }
            }
        }
        __syncthreads();
    }

    // ---- epilogue: add bias, write C ----
    const int rbase = r0 + wm + (lane >> 2);
    const int cbase = c0 + wn + (lane & 3) * 2;
#pragma unroll
    for (int j = 0; j < 4; ++j) {
        const int col = cbase + j * 8;
        const float bx = __ldg(&bias[col]);
        const float by = __ldg(&bias[col + 1]);
#pragma unroll
        for (int mt = 0; mt < 4; ++mt) {
            const int row = rbase + mt * 16;
            float2 v0 = make_float2(acc[mt][j][0] + bx, acc[mt][j][1] + by);
            float2 v1 = make_float2(acc[mt][j][2] + bx, acc[mt][j][3] + by);
            *reinterpret_cast<float2*>(&Cmat[(size_t)row * Nc + col]) = v0;
            *reinterpret_cast<float2*>(&Cmat[(size_t)(row + 8) * Nc + col]) = v1;
        }
    }
}

// ---------------------------------------------------------------------------
// Softmax over L*P=16 per (row, m) + loc computation.
// Reads the combined [off | attn] projection buffer.
// ---------------------------------------------------------------------------
__global__ void softmax_loc_kernel(const float* __restrict__ offattn,
                                   const float* __restrict__ ref_pts,
                                   float* __restrict__ loc_out,
                                   float* __restrict__ attn_out)
{
    const int row = blockIdx.x;
    const int t = threadIdx.x;

    float x = offattn[row * 256 + 128 + t];
    float mx = x;
#pragma unroll
    for (int o = 8; o >= 1; o >>= 1)
        mx = fmaxf(mx, __shfl_xor_sync(0xffffffffu, mx, o));
    float e = __expf(x - mx);
    float s = e;
#pragma unroll
    for (int o = 8; o >= 1; o >>= 1)
        s += __shfl_xor_sync(0xffffffffu, s, o);
    attn_out[row * MLP + t] = e / s;

    const int l = (t & 15) >> 2;
    const float Tf = (float)c_lens[l];
    const float ref = ref_pts[row * LL + l];
    loc_out[row * MLP + t] = ref + offattn[row * 256 + t] / Tf;
}

// ---------------------------------------------------------------------------
// Deformable sampling, float4 lanes: warp = (row, m); lane -> (sample slot,
// channel group). 8 lanes x 16B cover one 32-channel head row.
// ---------------------------------------------------------------------------
__global__ __launch_bounds__(256)
void deform_sample_kernel(const float* __restrict__ val,
                          const float* __restrict__ loc,
                          const float* __restrict__ attn,
                          float* __restrict__ mid)
{
    const int wid = threadIdx.x >> 5;
    const int lane = threadIdx.x & 31;
    const long long gw = (long long)blockIdx.x * 8 + wid;
    const int m = (int)(gw & 7);
    const int row = (int)(gw >> 3);
    const int n = row >> 11;
    const int sg = lane >> 3;       // sample slot 0..3
    const int cg = lane & 7;        // float4 channel group

    const float4* vb = reinterpret_cast<const float4*>(
        val + ((size_t)n * SS) * CC + m * DH) + cg;
    const int abase = row * MLP + m * 16;

    float4 acc = make_float4(0.f, 0.f, 0.f, 0.f);
#pragma unroll
    for (int g = 0; g < 4; ++g) {           // level == g
        const int i = g * 4 + sg;
        const int T = c_lens[g];
        const int st = c_start[g];
        const float lc = __ldg(&loc[abase + i]);
        const float aw = __ldg(&attn[abase + i]);
        const float pos = lc * (float)T - 0.5f;
        const float x0f = floorf(pos);
        const float fr = pos - x0f;
        const int x0 = (int)x0f;

        const float w0 = (x0 >= 0 && x0 < T) ? (1.f - fr) * aw : 0.f;
        const float w1 = (x0 + 1 >= 0 && x0 + 1 < T) ? fr * aw : 0.f;
        const int i0 = min(max(x0, 0), T - 1);
        const int i1 = min(max(x0 + 1, 0), T - 1);
        if (w0 != 0.f) {
            const float4 v = vb[(size_t)(st + i0) * (CC / 4)];
            acc.x += w0 * v.x; acc.y += w0 * v.y;
            acc.z += w0 * v.z; acc.w += w0 * v.w;
        }
        if (w1 != 0.f) {
            const float4 v = vb[(size_t)(st + i1) * (CC / 4)];
            acc.x += w1 * v.x; acc.y += w1 * v.y;
            acc.z += w1 * v.z; acc.w += w1 * v.w;
        }
    }
    // reduce across the 4 sample slots (xor 8, 16)
#pragma unroll
    for (int o = 8; o <= 16; o <<= 1) {
        acc.x += __shfl_xor_sync(0xffffffffu, acc.x, o);
        acc.y += __shfl_xor_sync(0xffffffffu, acc.y, o);
        acc.z += __shfl_xor_sync(0xffffffffu, acc.z, o);
        acc.w += __shfl_xor_sync(0xffffffffu, acc.w, o);
    }
    if (sg == 0)
        reinterpret_cast<float4*>(mid + (size_t)row * CC + m * DH)[cg] = acc;
}

// ---------------------------------------------------------------------------
extern "C" void kernel_launch(void* const* d_in, const int* in_sizes, int n_in,
                              void* d_out, int out_size)
{
    const float* query   = (const float*)d_in[0];
    const float* refpts  = (const float*)d_in[1];
    const float* in_flat = (const float*)d_in[2];
    const float* W_off   = (const float*)d_in[5];
    const float* b_off   = (const float*)d_in[6];
    const float* W_attn  = (const float*)d_in[7];
    const float* b_attn  = (const float*)d_in[8];
    const float* W_val   = (const float*)d_in[9];
    const float* b_val   = (const float*)d_in[10];
    const float* W_out   = (const float*)d_in[11];
    const float* b_out   = (const float*)d_in[12];

    float* out_main = (float*)d_out;
    float* out_loc  = out_main + (size_t)ROWS_Q * CC;
    float* out_attn = out_loc  + (size_t)ROWS_Q * MLP;

    float *d_val, *d_offattn, *d_mid, *d_bcat;
    __nv_bfloat16 *d_in_h, *d_in_l, *d_q_h, *d_q_l, *d_mid_h, *d_mid_l;
    __nv_bfloat16 *d_wv_h, *d_wv_l, *d_wcat_h, *d_wcat_l, *d_wo_h, *d_wo_l;
    cudaGetSymbolAddress((void**)&d_val,     g_val);
    cudaGetSymbolAddress((void**)&d_offattn, g_offattn);
    cudaGetSymbolAddress((void**)&d_mid,     g_mid);
    cudaGetSymbolAddress((void**)&d_bcat,    g_bcat);
    cudaGetSymbolAddress((void**)&d_in_h,    g_in_h);
    cudaGetSymbolAddress((void**)&d_in_l,    g_in_l);
    cudaGetSymbolAddress((void**)&d_q_h,     g_q_h);
    cudaGetSymbolAddress((void**)&d_q_l,     g_q_l);
    cudaGetSymbolAddress((void**)&d_mid_h,   g_mid_h);
    cudaGetSymbolAddress((void**)&d_mid_l,   g_mid_l);
    cudaGetSymbolAddress((void**)&d_wv_h,    g_wv_h);
    cudaGetSymbolAddress((void**)&d_wv_l,    g_wv_l);
    cudaGetSymbolAddress((void**)&d_wcat_h,  g_wcat_h);
    cudaGetSymbolAddress((void**)&d_wcat_l,  g_wcat_l);
    cudaGetSymbolAddress((void**)&d_wo_h,    g_wo_h);
    cudaGetSymbolAddress((void**)&d_wo_l,    g_wo_l);

    static bool attr_set = false;
    if (!attr_set) {
        cudaFuncSetAttribute(gemm_bf16v2,
                             cudaFuncAttributeMaxDynamicSharedMemorySize,
                             GEMM_SMEM);
        attr_set = true;
    }

    // --- conversions (all independent) ---
    convert_act<<<2048, 256>>>(in_flat, d_in_h, d_in_l, ROWS_V * CC / 4);
    convert_act<<<2048, 256>>>(query,   d_q_h,  d_q_l,  ROWS_Q * CC / 4);
    convert_wt<<<dim3(CC / 64, CC / 64), 256>>>(W_val, d_wv_h, d_wv_l, CC, CC);
    convert_wt<<<dim3(2, 4), 256>>>(W_off,  d_wcat_h,            d_wcat_l,            CC, 128);
    convert_wt<<<dim3(2, 4), 256>>>(W_attn, d_wcat_h + 128 * CC, d_wcat_l + 128 * CC, CC, 128);
    convert_wt<<<dim3(CC / 64, CC / 64), 256>>>(W_out, d_wo_h, d_wo_l, CC, CC);
    bias_cat<<<1, 256>>>(b_off, b_attn, d_bcat);

    // 1) value projection: (30720 x 256) @ (256 x 256)
    gemm_bf16v2<<<dim3(2, ROWS_V / 128), 256, GEMM_SMEM>>>(
        d_in_h, d_in_l, d_wv_h, d_wv_l, b_val, d_val, ROWS_V, CC, CC);
    // 2) fused offset+attn projection: (16384 x 256) @ (256 x 256)
    gemm_bf16v2<<<dim3(2, ROWS_Q / 128), 256, GEMM_SMEM>>>(
        d_q_h, d_q_l, d_wcat_h, d_wcat_l, d_bcat, d_offattn, ROWS_Q, 256, CC);
    // 3) softmax + loc
    softmax_loc_kernel<<<ROWS_Q, 128>>>(d_offattn, refpts, out_loc, out_attn);
    // 4) deformable sampling
    deform_sample_kernel<<<ROWS_Q, 256>>>(d_val, out_loc, out_attn, d_mid);
    // 5) convert mid, then output projection -> out_main
    convert_act<<<2048, 256>>>(d_mid, d_mid_h, d_mid_l, ROWS_Q * CC / 4);
    gemm_bf16v2<<<dim3(2, ROWS_Q / 128), 256, GEMM_SMEM>>>(
        d_mid_h, d_mid_l, d_wo_h, d_wo_l, b_out, out_main, ROWS_Q, CC, CC);
}

// round 11
// speedup vs baseline: 2.2294x; 1.1375x over previous
#include <cuda_runtime.h>
#include <cuda_bf16.h>
#include <cstdint>

// Problem constants (fixed shapes per reference)
#define NB   8
#define LQ   2048
#define CC   256
#define MM   8
#define LL   4
#define PP   4
#define DH   32
#define SS   3840
#define ROWS_Q (NB * LQ)     // 16384
#define ROWS_V (NB * SS)     // 30720
#define MLP  (MM * LL * PP)  // 128

__constant__ int c_lens[4]  = {2048, 1024, 512, 256};
__constant__ int c_start[4] = {0, 2048, 3072, 3584};

// ---------------------------------------------------------------------------
// Scratch (device globals; no allocation allowed)
// ---------------------------------------------------------------------------
__device__ float g_val[ROWS_V * CC];           // value projection (fp32)
__device__ float g_offattn[ROWS_Q * 256];      // [off | attn logits]

__device__ __nv_bfloat16 g_in_h[ROWS_V * CC];  // in_flatten hi/lo
__device__ __nv_bfloat16 g_in_l[ROWS_V * CC];
__device__ __nv_bfloat16 g_q_h[ROWS_Q * CC];   // query hi/lo
__device__ __nv_bfloat16 g_q_l[ROWS_Q * CC];
__device__ __nv_bfloat16 g_mid_h[ROWS_Q * CC]; // mid hi/lo (written by deform)
__device__ __nv_bfloat16 g_mid_l[ROWS_Q * CC];

__device__ __nv_bfloat16 g_wv_h[CC * CC],   g_wv_l[CC * CC];    // W_val^T
__device__ __nv_bfloat16 g_wcat_h[CC * CC], g_wcat_l[CC * CC];  // [W_off|W_attn]^T
__device__ __nv_bfloat16 g_wo_h[CC * CC],   g_wo_l[CC * CC];    // W_out^T
__device__ float g_bcat[256];

// ---------------------------------------------------------------------------
// helpers
// ---------------------------------------------------------------------------
static __device__ __forceinline__ uint32_t smem_u32(const void* p) {
    uint32_t a;
    asm("{ .reg .u64 t; cvta.to.shared.u64 t, %1; cvt.u32.u64 %0, t; }"
        : "=r"(a) : "l"(p));
    return a;
}
static __device__ __forceinline__ uint32_t swz128(uint32_t off) {
    return off ^ ((off >> 3) & 0x70);
}
static __device__ __forceinline__ uint32_t pack_hi(float a, float b,
                                                   float& la, float& lb) {
    __nv_bfloat16 ha = __float2bfloat16(a);
    __nv_bfloat16 hb = __float2bfloat16(b);
    la = a - __bfloat162float(ha);
    lb = b - __bfloat162float(hb);
    return (uint32_t)__bfloat16_as_ushort(ha) |
           ((uint32_t)__bfloat16_as_ushort(hb) << 16);
}
static __device__ __forceinline__ uint32_t pack_bf(float a, float b) {
    return (uint32_t)__bfloat16_as_ushort(__float2bfloat16(a)) |
           ((uint32_t)__bfloat16_as_ushort(__float2bfloat16(b)) << 16);
}

#define LDMX4(r0, r1, r2, r3, addr) \
    asm volatile("ldmatrix.sync.aligned.m8n8.x4.shared.b16 {%0,%1,%2,%3}, [%4];" \
                 : "=r"(r0), "=r"(r1), "=r"(r2), "=r"(r3) : "r"(addr))

#define MMA16816(c, a, b0, b1) \
    asm volatile("mma.sync.aligned.m16n8k16.row.col.f32.bf16.bf16.f32 " \
                 "{%0,%1,%2,%3}, {%4,%5,%6,%7}, {%8,%9}, {%0,%1,%2,%3};" \
                 : "+f"((c)[0]), "+f"((c)[1]), "+f"((c)[2]), "+f"((c)[3]) \
                 : "r"((a)[0]), "r"((a)[1]), "r"((a)[2]), "r"((a)[3]), \
                   "r"(b0), "r"(b1))

#define CP16(dst, src) \
    asm volatile("cp.async.cg.shared.global [%0], [%1], 16;" \
                 :: "r"(dst), "l"(src))
#define CP_COMMIT() asm volatile("cp.async.commit_group;" ::: "memory")
#define CP_WAIT(n)  asm volatile("cp.async.wait_group %0;" :: "n"(n) : "memory")

// ===========================================================================
// Conversion: both activation tensors in one launch (grid-stride over the
// concatenated float4 range).
// ===========================================================================
__global__ void convert_act2(const float* __restrict__ s1,
                             __nv_bfloat16* __restrict__ h1,
                             __nv_bfloat16* __restrict__ l1, int n4a,
                             const float* __restrict__ s2,
                             __nv_bfloat16* __restrict__ h2,
                             __nv_bfloat16* __restrict__ l2, int n4b)
{
    int i = blockIdx.x * blockDim.x + threadIdx.x;
    const int stride = gridDim.x * blockDim.x;
    const int tot = n4a + n4b;
    for (; i < tot; i += stride) {
        const float* src;
        uint2 *ho, *lo;
        int j;
        if (i < n4a) { src = s1; j = i;        ho = (uint2*)h1; lo = (uint2*)l1; }
        else         { src = s2; j = i - n4a;  ho = (uint2*)h2; lo = (uint2*)l2; }
        const float4 v = reinterpret_cast<const float4*>(src)[j];
        float l0, l1f, l2f, l3;
        const uint32_t h01 = pack_hi(v.x, v.y, l0, l1f);
        const uint32_t h23 = pack_hi(v.z, v.w, l2f, l3);
        ho[j] = make_uint2(h01, h23);
        lo[j] = make_uint2(pack_bf(l0, l1f), pack_bf(l2f, l3));
    }
}

// ===========================================================================
// All weight transpose+convert + bias concat in ONE launch (48 blocks).
// Block mapping: [0,16) W_val, [16,24) W_off, [24,32) W_attn, [32,48) W_out.
// ===========================================================================
__global__ __launch_bounds__(256)
void convert_wts_all(const float* __restrict__ W_val,
                     const float* __restrict__ W_off,
                     const float* __restrict__ W_attn,
                     const float* __restrict__ W_out,
                     __nv_bfloat16* __restrict__ wv_h,  __nv_bfloat16* __restrict__ wv_l,
                     __nv_bfloat16* __restrict__ wc_h,  __nv_bfloat16* __restrict__ wc_l,
                     __nv_bfloat16* __restrict__ wo_h,  __nv_bfloat16* __restrict__ wo_l,
                     const float* __restrict__ b_off,
                     const float* __restrict__ b_attn,
                     float* __restrict__ bcat)
{
    __shared__ float s[64][65];
    const int b = blockIdx.x;
    const int t = threadIdx.x;

    const float* W;
    __nv_bfloat16 *Th, *Tl;
    int N, local;
    if (b < 16)      { W = W_val;  Th = wv_h;            Tl = wv_l;            N = 256; local = b; }
    else if (b < 24) { W = W_off;  Th = wc_h;            Tl = wc_l;            N = 128; local = b - 16; }
    else if (b < 32) { W = W_attn; Th = wc_h + 128 * CC; Tl = wc_l + 128 * CC; N = 128; local = b - 24; }
    else             { W = W_out;  Th = wo_h;            Tl = wo_l;            N = 256; local = b - 32; }
    const int ntiles = N >> 6;
    const int n0 = (local % ntiles) * 64;
    const int k0 = (local / ntiles) * 64;

    if (b == 0) bcat[t] = (t < 128) ? b_off[t] : b_attn[t - 128];

#pragma unroll
    for (int j = 0; j < 16; ++j) {
        const int idx = t + j * 256;
        const int r = idx >> 6, c = idx & 63;
        s[r][c] = W[(size_t)(k0 + r) * N + n0 + c];
    }
    __syncthreads();
#pragma unroll
    for (int j = 0; j < 16; ++j) {
        const int idx = t + j * 256;
        const int r = idx >> 6, c = idx & 63;
        const float v = s[c][r];
        const __nv_bfloat16 h = __float2bfloat16(v);
        const float l = v - __bfloat162float(h);
        Th[(size_t)(n0 + r) * CC + k0 + c] = h;
        Tl[(size_t)(n0 + r) * CC + k0 + c] = __float2bfloat16(l);
    }
}

// ===========================================================================
// Pipelined bf16 GEMM (mma.sync, hi/lo split, fp32 accumulate):
// C[Mr,Nc] = A[Mr,K] @ B^T[Nc,K] + bias.   A,B in bf16 hi/lo; K%64==0.
// Tile 128x128, 8 warps (2m x 4n of 64x32), K chunks of 64, 2-stage cp.async.
// ===========================================================================
#define STG_SZ  65536
#define T_AH    0
#define T_AL    16384
#define T_BH    32768
#define T_BL    49152
#define GEMM_SMEM (2 * STG_SZ)

__global__ __launch_bounds__(256)
void gemm_bf16v2(const __nv_bfloat16* __restrict__ Ah,
                 const __nv_bfloat16* __restrict__ Al,
                 const __nv_bfloat16* __restrict__ Bh,
                 const __nv_bfloat16* __restrict__ Bl,
                 const float* __restrict__ bias, float* __restrict__ Cmat,
                 int Mr, int Nc, int K)
{
    extern __shared__ char smem[];
    const uint32_t sb = smem_u32(smem);
    const int tid = threadIdx.x;
    const int lane = tid & 31, wid = tid >> 5;
    const int r0 = blockIdx.y * 128, c0 = blockIdx.x * 128;
    const int wm = (wid >> 2) * 64;
    const int wn = (wid & 3) * 32;

    float acc[4][4][4];
#pragma unroll
    for (int mt = 0; mt < 4; ++mt)
#pragma unroll
        for (int j = 0; j < 4; ++j)
#pragma unroll
            for (int r = 0; r < 4; ++r) acc[mt][j][r] = 0.f;

    const __nv_bfloat16* srcs[4] = {Ah, Al, Bh, Bl};

    auto load_chunk = [&](int k0, uint32_t stgBase) {
#pragma unroll
        for (int j = 0; j < 16; ++j) {
            const int seg = tid + j * 256;
            const int tile = seg >> 10;
            const int row = (seg & 1023) >> 3;
            const int s8 = seg & 7;
            const int grow = (tile < 2) ? (r0 + row) : (c0 + row);
            const __nv_bfloat16* src =
                srcs[tile] + (size_t)grow * K + k0 + s8 * 8;
            const uint32_t dst =
                stgBase + tile * 16384 + swz128((uint32_t)(row * 128 + s8 * 16));
            CP16(dst, src);
        }
        CP_COMMIT();
    };

    const int matq = lane >> 3, rq = lane & 7;
    uint32_t aRowB[4], bRowB[2];
#pragma unroll
    for (int mt = 0; mt < 4; ++mt)
        aRowB[mt] = (uint32_t)((wm + mt * 16 + (matq & 1) * 8 + rq) * 128 +
                               (matq >> 1) * 16);
#pragma unroll
    for (int nt = 0; nt < 2; ++nt)
        bRowB[nt] = (uint32_t)((wn + nt * 16 + (matq >> 1) * 8 + rq) * 128 +
                               (matq & 1) * 16);

    const int nch = K >> 6;
    load_chunk(0, sb);

    for (int ch = 0; ch < nch; ++ch) {
        const uint32_t stg = sb + (uint32_t)(ch & 1) * STG_SZ;
        if (ch + 1 < nch) {
            load_chunk((ch + 1) << 6, sb + (uint32_t)((ch + 1) & 1) * STG_SZ);
            CP_WAIT(1);
        } else {
            CP_WAIT(0);
        }
        __syncthreads();

#pragma unroll
        for (int ks = 0; ks < 4; ++ks) {
            uint32_t ah[4][4], al[4][4], bh[2][4], bl[2][4];
#pragma unroll
            for (int mt = 0; mt < 4; ++mt) {
                const uint32_t off = swz128(aRowB[mt] + ks * 32);
                LDMX4(ah[mt][0], ah[mt][1], ah[mt][2], ah[mt][3],
                      stg + T_AH + off);
                LDMX4(al[mt][0], al[mt][1], al[mt][2], al[mt][3],
                      stg + T_AL + off);
            }
#pragma unroll
            for (int nt = 0; nt < 2; ++nt) {
                const uint32_t off = swz128(bRowB[nt] + ks * 32);
                LDMX4(bh[nt][0], bh[nt][1], bh[nt][2], bh[nt][3],
                      stg + T_BH + off);
                LDMX4(bl[nt][0], bl[nt][1], bl[nt][2], bl[nt][3],
                      stg + T_BL + off);
            }
#pragma unroll
            for (int mt = 0; mt < 4; ++mt) {
#pragma unroll
                for (int nt = 0; nt < 2; ++nt) {
#pragma unroll
                    for (int h = 0; h < 2; ++h) {
                        const int j = nt * 2 + h;
                        MMA16816(acc[mt][j], ah[mt], bh[nt][2 * h], bh[nt][2 * h + 1]);
                        MMA16816(acc[mt][j], ah[mt], bl[nt][2 * h], bl[nt][2 * h + 1]);
                        MMA16816(acc[mt][j], al[mt], bh[nt][2 * h], bh[nt][2 * h + 1]);
                    }
                }
            }
        }
        __syncthreads();
    }

    const int rbase = r0 + wm + (lane >> 2);
    const int cbase = c0 + wn + (lane & 3) * 2;
#pragma unroll
    for (int j = 0; j < 4; ++j) {
        const int col = cbase + j * 8;
        const float bx = __ldg(&bias[col]);
        const float by = __ldg(&bias[col + 1]);
#pragma unroll
        for (int mt = 0; mt < 4; ++mt) {
            const int row = rbase + mt * 16;
            float2 v0 = make_float2(acc[mt][j][0] + bx, acc[mt][j][1] + by);
            float2 v1 = make_float2(acc[mt][j][2] + bx, acc[mt][j][3] + by);
            *reinterpret_cast<float2*>(&Cmat[(size_t)row * Nc + col]) = v0;
            *reinterpret_cast<float2*>(&Cmat[(size_t)(row + 8) * Nc + col]) = v1;
        }
    }
}

// ===========================================================================
// Fused softmax + loc + deformable sampling + mid bf16-split epilogue.
// One warp per (row, m). Lane layout: sg = lane>>3 (sample slot 0..3),
// cg = lane&7 (float4 channel group). Each lane owns logits i = g*4+sg for
// g=0..3; warp softmax over the 16 logits via local-4 + shfl.xor(8,16).
// Writes loc/attn output regions AND samples, then writes mid as bf16 hi/lo.
// ===========================================================================
__global__ __launch_bounds__(256)
void deform_fused(const float* __restrict__ val,
                  const float* __restrict__ offattn,
                  const float* __restrict__ refpts,
                  float* __restrict__ loc_out,
                  float* __restrict__ attn_out,
                  __nv_bfloat16* __restrict__ mid_h,
                  __nv_bfloat16* __restrict__ mid_l)
{
    const int wid = threadIdx.x >> 5;
    const int lane = threadIdx.x & 31;
    const long long gw = (long long)blockIdx.x * 8 + wid;
    const int m = (int)(gw & 7);
    const int row = (int)(gw >> 3);
    const int n = row >> 11;
    const int sg = lane >> 3;       // sample slot 0..3
    const int cg = lane & 7;        // float4 channel group

    // --- softmax over 16 logits + loc ---
    const int oroW = row * 256 + m * 16;
    float logit[4], offv[4];
#pragma unroll
    for (int g = 0; g < 4; ++g) {
        const int i = g * 4 + sg;
        offv[g]  = __ldg(&offattn[oroW + i]);
        logit[g] = __ldg(&offattn[oroW + 128 + i]);
    }
    float mx = fmaxf(fmaxf(logit[0], logit[1]), fmaxf(logit[2], logit[3]));
    mx = fmaxf(mx, __shfl_xor_sync(0xffffffffu, mx, 8));
    mx = fmaxf(mx, __shfl_xor_sync(0xffffffffu, mx, 16));
    float e[4], s = 0.f;
#pragma unroll
    for (int g = 0; g < 4; ++g) { e[g] = __expf(logit[g] - mx); s += e[g]; }
    s += __shfl_xor_sync(0xffffffffu, s, 8);
    s += __shfl_xor_sync(0xffffffffu, s, 16);

    float aw[4], lc[4];
#pragma unroll
    for (int g = 0; g < 4; ++g) {
        aw[g] = e[g] / s;
        lc[g] = __ldg(&refpts[row * LL + g]) + offv[g] / (float)c_lens[g];
    }
    if (cg == 0) {
        const int ob = row * MLP + m * 16;
#pragma unroll
        for (int g = 0; g < 4; ++g) {
            attn_out[ob + g * 4 + sg] = aw[g];
            loc_out[ob + g * 4 + sg]  = lc[g];
        }
    }

    // --- sampling ---
    const float4* vb = reinterpret_cast<const float4*>(
        val + ((size_t)n * SS) * CC + m * DH) + cg;

    float4 acc = make_float4(0.f, 0.f, 0.f, 0.f);
#pragma unroll
    for (int g = 0; g < 4; ++g) {           // level == g
        const int T = c_lens[g];
        const int st = c_start[g];
        const float pos = lc[g] * (float)T - 0.5f;
        const float x0f = floorf(pos);
        const float fr = pos - x0f;
        const int x0 = (int)x0f;

        const float w0 = (x0 >= 0 && x0 < T) ? (1.f - fr) * aw[g] : 0.f;
        const float w1 = (x0 + 1 >= 0 && x0 + 1 < T) ? fr * aw[g] : 0.f;
        const int i0 = min(max(x0, 0), T - 1);
        const int i1 = min(max(x0 + 1, 0), T - 1);
        if (w0 != 0.f) {
            const float4 v = vb[(size_t)(st + i0) * (CC / 4)];
            acc.x += w0 * v.x; acc.y += w0 * v.y;
            acc.z += w0 * v.z; acc.w += w0 * v.w;
        }
        if (w1 != 0.f) {
            const float4 v = vb[(size_t)(st + i1) * (CC / 4)];
            acc.x += w1 * v.x; acc.y += w1 * v.y;
            acc.z += w1 * v.z; acc.w += w1 * v.w;
        }
    }
#pragma unroll
    for (int o = 8; o <= 16; o <<= 1) {
        acc.x += __shfl_xor_sync(0xffffffffu, acc.x, o);
        acc.y += __shfl_xor_sync(0xffffffffu, acc.y, o);
        acc.z += __shfl_xor_sync(0xffffffffu, acc.z, o);
        acc.w += __shfl_xor_sync(0xffffffffu, acc.w, o);
    }
    if (sg == 0) {
        // bf16 hi/lo split epilogue for the W_out GEMM
        float l0, l1, l2, l3;
        const uint32_t h01 = pack_hi(acc.x, acc.y, l0, l1);
        const uint32_t h23 = pack_hi(acc.z, acc.w, l2, l3);
        const size_t base = (size_t)row * CC + m * DH + cg * 4;
        *reinterpret_cast<uint2*>(&mid_h[base]) = make_uint2(h01, h23);
        *reinterpret_cast<uint2*>(&mid_l[base]) =
            make_uint2(pack_bf(l0, l1), pack_bf(l2, l3));
    }
}

// ---------------------------------------------------------------------------
extern "C" void kernel_launch(void* const* d_in, const int* in_sizes, int n_in,
                              void* d_out, int out_size)
{
    const float* query   = (const float*)d_in[0];
    const float* refpts  = (const float*)d_in[1];
    const float* in_flat = (const float*)d_in[2];
    const float* W_off   = (const float*)d_in[5];
    const float* b_off   = (const float*)d_in[6];
    const float* W_attn  = (const float*)d_in[7];
    const float* b_attn  = (const float*)d_in[8];
    const float* W_val   = (const float*)d_in[9];
    const float* b_val   = (const float*)d_in[10];
    const float* W_out   = (const float*)d_in[11];
    const float* b_out   = (const float*)d_in[12];

    float* out_main = (float*)d_out;
    float* out_loc  = out_main + (size_t)ROWS_Q * CC;
    float* out_attn = out_loc  + (size_t)ROWS_Q * MLP;

    float *d_val, *d_offattn, *d_bcat;
    __nv_bfloat16 *d_in_h, *d_in_l, *d_q_h, *d_q_l, *d_mid_h, *d_mid_l;
    __nv_bfloat16 *d_wv_h, *d_wv_l, *d_wcat_h, *d_wcat_l, *d_wo_h, *d_wo_l;
    cudaGetSymbolAddress((void**)&d_val,     g_val);
    cudaGetSymbolAddress((void**)&d_offattn, g_offattn);
    cudaGetSymbolAddress((void**)&d_bcat,    g_bcat);
    cudaGetSymbolAddress((void**)&d_in_h,    g_in_h);
    cudaGetSymbolAddress((void**)&d_in_l,    g_in_l);
    cudaGetSymbolAddress((void**)&d_q_h,     g_q_h);
    cudaGetSymbolAddress((void**)&d_q_l,     g_q_l);
    cudaGetSymbolAddress((void**)&d_mid_h,   g_mid_h);
    cudaGetSymbolAddress((void**)&d_mid_l,   g_mid_l);
    cudaGetSymbolAddress((void**)&d_wv_h,    g_wv_h);
    cudaGetSymbolAddress((void**)&d_wv_l,    g_wv_l);
    cudaGetSymbolAddress((void**)&d_wcat_h,  g_wcat_h);
    cudaGetSymbolAddress((void**)&d_wcat_l,  g_wcat_l);
    cudaGetSymbolAddress((void**)&d_wo_h,    g_wo_h);
    cudaGetSymbolAddress((void**)&d_wo_l,    g_wo_l);

    static bool attr_set = false;
    if (!attr_set) {
        cudaFuncSetAttribute(gemm_bf16v2,
                             cudaFuncAttributeMaxDynamicSharedMemorySize,
                             GEMM_SMEM);
        attr_set = true;
    }

    // 1) all activation conversions (one launch)
    convert_act2<<<2048, 256>>>(in_flat, d_in_h, d_in_l, ROWS_V * CC / 4,
                                query,   d_q_h,  d_q_l,  ROWS_Q * CC / 4);
    // 2) all weight conversions + bias concat (one launch)
    convert_wts_all<<<48, 256>>>(W_val, W_off, W_attn, W_out,
                                 d_wv_h, d_wv_l, d_wcat_h, d_wcat_l,
                                 d_wo_h, d_wo_l, b_off, b_attn, d_bcat);
    // 3) value projection: (30720 x 256) @ (256 x 256)
    gemm_bf16v2<<<dim3(2, ROWS_V / 128), 256, GEMM_SMEM>>>(
        d_in_h, d_in_l, d_wv_h, d_wv_l, b_val, d_val, ROWS_V, CC, CC);
    // 4) fused offset+attn projection: (16384 x 256) @ (256 x 256)
    gemm_bf16v2<<<dim3(2, ROWS_Q / 128), 256, GEMM_SMEM>>>(
        d_q_h, d_q_l, d_wcat_h, d_wcat_l, d_bcat, d_offattn, ROWS_Q, 256, CC);
    // 5) fused softmax + loc + sampling + mid bf16 split
    deform_fused<<<ROWS_Q, 256>>>(d_val, d_offattn, refpts,
                                  out_loc, out_attn, d_mid_h, d_mid_l);
    // 6) output projection -> out_main
    gemm_bf16v2<<<dim3(2, ROWS_Q / 128), 256, GEMM_SMEM>>>(
        d_mid_h, d_mid_l, d_wo_h, d_wo_l, b_out, out_main, ROWS_Q, CC, CC);
}

// round 13
// speedup vs baseline: 2.3549x; 1.0563x over previous
#include <cuda_runtime.h>
#include <cuda_bf16.h>
#include <cstdint>

// Problem constants (fixed shapes per reference)
#define NB   8
#define LQ   2048
#define CC   256
#define MM   8
#define LL   4
#define PP   4
#define DH   32
#define SS   3840
#define ROWS_Q (NB * LQ)     // 16384
#define ROWS_V (NB * SS)     // 30720
#define MLP  (MM * LL * PP)  // 128

__constant__ int c_lens[4]  = {2048, 1024, 512, 256};
__constant__ int c_start[4] = {0, 2048, 3072, 3584};

// ---------------------------------------------------------------------------
// Scratch (device globals; no allocation allowed)
// ---------------------------------------------------------------------------
__device__ float g_val[ROWS_V * CC];           // value projection (fp32)
__device__ float g_offattn[ROWS_Q * 256];      // [off | attn logits]

__device__ __nv_bfloat16 g_in_h[ROWS_V * CC];  // in_flatten hi/lo
__device__ __nv_bfloat16 g_in_l[ROWS_V * CC];
__device__ __nv_bfloat16 g_q_h[ROWS_Q * CC];   // query hi/lo
__device__ __nv_bfloat16 g_q_l[ROWS_Q * CC];
__device__ __nv_bfloat16 g_mid_h[ROWS_Q * CC]; // mid hi/lo (written by deform)
__device__ __nv_bfloat16 g_mid_l[ROWS_Q * CC];

__device__ __nv_bfloat16 g_wv_h[CC * CC],   g_wv_l[CC * CC];    // W_val^T
__device__ __nv_bfloat16 g_wcat_h[CC * CC], g_wcat_l[CC * CC];  // [W_off|W_attn]^T
__device__ __nv_bfloat16 g_wo_h[CC * CC],   g_wo_l[CC * CC];    // W_out^T
__device__ float g_bcat[256];

// ---------------------------------------------------------------------------
// helpers
// ---------------------------------------------------------------------------
static __device__ __forceinline__ uint32_t smem_u32(const void* p) {
    uint32_t a;
    asm("{ .reg .u64 t; cvta.to.shared.u64 t, %1; cvt.u32.u64 %0, t; }"
        : "=r"(a) : "l"(p));
    return a;
}
static __device__ __forceinline__ uint32_t swz128(uint32_t off) {
    return off ^ ((off >> 3) & 0x70);
}
static __device__ __forceinline__ uint32_t pack_hi(float a, float b,
                                                   float& la, float& lb) {
    __nv_bfloat16 ha = __float2bfloat16(a);
    __nv_bfloat16 hb = __float2bfloat16(b);
    la = a - __bfloat162float(ha);
    lb = b - __bfloat162float(hb);
    return (uint32_t)__bfloat16_as_ushort(ha) |
           ((uint32_t)__bfloat16_as_ushort(hb) << 16);
}
static __device__ __forceinline__ uint32_t pack_bf(float a, float b) {
    return (uint32_t)__bfloat16_as_ushort(__float2bfloat16(a)) |
           ((uint32_t)__bfloat16_as_ushort(__float2bfloat16(b)) << 16);
}

#define LDMX4(r0, r1, r2, r3, addr) \
    asm volatile("ldmatrix.sync.aligned.m8n8.x4.shared.b16 {%0,%1,%2,%3}, [%4];" \
                 : "=r"(r0), "=r"(r1), "=r"(r2), "=r"(r3) : "r"(addr))

#define MMA16816(c, a, b0, b1) \
    asm volatile("mma.sync.aligned.m16n8k16.row.col.f32.bf16.bf16.f32 " \
                 "{%0,%1,%2,%3}, {%4,%5,%6,%7}, {%8,%9}, {%0,%1,%2,%3};" \
                 : "+f"((c)[0]), "+f"((c)[1]), "+f"((c)[2]), "+f"((c)[3]) \
                 : "r"((a)[0]), "r"((a)[1]), "r"((a)[2]), "r"((a)[3]), \
                   "r"(b0), "r"(b1))

#define CP16(dst, src) \
    asm volatile("cp.async.cg.shared.global [%0], [%1], 16;" \
                 :: "r"(dst), "l"(src))
#define CP_COMMIT() asm volatile("cp.async.commit_group;" ::: "memory")
#define CP_WAIT(n)  asm volatile("cp.async.wait_group %0;" :: "n"(n) : "memory")

// ===========================================================================
// Activation fp32 -> bf16 hi/lo conversion (one tensor per launch).
// ===========================================================================
__global__ void convert_act(const float* __restrict__ src,
                            __nv_bfloat16* __restrict__ hi,
                            __nv_bfloat16* __restrict__ lo, int n4)
{
    int i = blockIdx.x * blockDim.x + threadIdx.x;
    const int stride = gridDim.x * blockDim.x;
    for (; i < n4; i += stride) {
        const float4 v = reinterpret_cast<const float4*>(src)[i];
        float l0, l1f, l2f, l3;
        const uint32_t h01 = pack_hi(v.x, v.y, l0, l1f);
        const uint32_t h23 = pack_hi(v.z, v.w, l2f, l3);
        reinterpret_cast<uint2*>(hi)[i] = make_uint2(h01, h23);
        reinterpret_cast<uint2*>(lo)[i] = make_uint2(pack_bf(l0, l1f),
                                                     pack_bf(l2f, l3));
    }
}

// ===========================================================================
// All weight transpose+convert + bias concat in ONE launch (48 blocks).
// ===========================================================================
__global__ __launch_bounds__(256)
void convert_wts_all(const float* __restrict__ W_val,
                     const float* __restrict__ W_off,
                     const float* __restrict__ W_attn,
                     const float* __restrict__ W_out,
                     __nv_bfloat16* __restrict__ wv_h,  __nv_bfloat16* __restrict__ wv_l,
                     __nv_bfloat16* __restrict__ wc_h,  __nv_bfloat16* __restrict__ wc_l,
                     __nv_bfloat16* __restrict__ wo_h,  __nv_bfloat16* __restrict__ wo_l,
                     const float* __restrict__ b_off,
                     const float* __restrict__ b_attn,
                     float* __restrict__ bcat)
{
    __shared__ float s[64][65];
    const int b = blockIdx.x;
    const int t = threadIdx.x;

    const float* W;
    __nv_bfloat16 *Th, *Tl;
    int N, local;
    if (b < 16)      { W = W_val;  Th = wv_h;            Tl = wv_l;            N = 256; local = b; }
    else if (b < 24) { W = W_off;  Th = wc_h;            Tl = wc_l;            N = 128; local = b - 16; }
    else if (b < 32) { W = W_attn; Th = wc_h + 128 * CC; Tl = wc_l + 128 * CC; N = 128; local = b - 24; }
    else             { W = W_out;  Th = wo_h;            Tl = wo_l;            N = 256; local = b - 32; }
    const int ntiles = N >> 6;
    const int n0 = (local % ntiles) * 64;
    const int k0 = (local / ntiles) * 64;

    if (b == 0) bcat[t] = (t < 128) ? b_off[t] : b_attn[t - 128];

#pragma unroll
    for (int j = 0; j < 16; ++j) {
        const int idx = t + j * 256;
        const int r = idx >> 6, c = idx & 63;
        s[r][c] = W[(size_t)(k0 + r) * N + n0 + c];
    }
    __syncthreads();
#pragma unroll
    for (int j = 0; j < 16; ++j) {
        const int idx = t + j * 256;
        const int r = idx >> 6, c = idx & 63;
        const float v = s[c][r];
        const __nv_bfloat16 h = __float2bfloat16(v);
        const float l = v - __bfloat162float(h);
        Th[(size_t)(n0 + r) * CC + k0 + c] = h;
        Tl[(size_t)(n0 + r) * CC + k0 + c] = __float2bfloat16(l);
    }
}

// ===========================================================================
// Pipelined bf16 GEMM (mma.sync, hi/lo split, fp32 accumulate):
// C[Mr,Nc] = A[Mr,K] @ B^T[Nc,K] + bias.   A,B in bf16 hi/lo; K%64==0.
// Tile 128x128, 8 warps (2m x 4n of 64x32), K chunks of 64, 2-stage cp.async.
// ===========================================================================
#define STG_SZ  65536
#define T_AH    0
#define T_AL    16384
#define T_BH    32768
#define T_BL    49152
#define GEMM_SMEM (2 * STG_SZ)

__global__ __launch_bounds__(256)
void gemm_bf16v2(const __nv_bfloat16* __restrict__ Ah,
                 const __nv_bfloat16* __restrict__ Al,
                 const __nv_bfloat16* __restrict__ Bh,
                 const __nv_bfloat16* __restrict__ Bl,
                 const float* __restrict__ bias, float* __restrict__ Cmat,
                 int Mr, int Nc, int K)
{
    extern __shared__ char smem[];
    const uint32_t sb = smem_u32(smem);
    const int tid = threadIdx.x;
    const int lane = tid & 31, wid = tid >> 5;
    const int r0 = blockIdx.y * 128, c0 = blockIdx.x * 128;
    const int wm = (wid >> 2) * 64;
    const int wn = (wid & 3) * 32;

    float acc[4][4][4];
#pragma unroll
    for (int mt = 0; mt < 4; ++mt)
#pragma unroll
        for (int j = 0; j < 4; ++j)
#pragma unroll
            for (int r = 0; r < 4; ++r) acc[mt][j][r] = 0.f;

    const __nv_bfloat16* srcs[4] = {Ah, Al, Bh, Bl};

    auto load_chunk = [&](int k0, uint32_t stgBase) {
#pragma unroll
        for (int j = 0; j < 16; ++j) {
            const int seg = tid + j * 256;
            const int tile = seg >> 10;
            const int row = (seg & 1023) >> 3;
            const int s8 = seg & 7;
            const int grow = (tile < 2) ? (r0 + row) : (c0 + row);
            const __nv_bfloat16* src =
                srcs[tile] + (size_t)grow * K + k0 + s8 * 8;
            const uint32_t dst =
                stgBase + tile * 16384 + swz128((uint32_t)(row * 128 + s8 * 16));
            CP16(dst, src);
        }
        CP_COMMIT();
    };

    const int matq = lane >> 3, rq = lane & 7;
    uint32_t aRowB[4], bRowB[2];
#pragma unroll
    for (int mt = 0; mt < 4; ++mt)
        aRowB[mt] = (uint32_t)((wm + mt * 16 + (matq & 1) * 8 + rq) * 128 +
                               (matq >> 1) * 16);
#pragma unroll
    for (int nt = 0; nt < 2; ++nt)
        bRowB[nt] = (uint32_t)((wn + nt * 16 + (matq >> 1) * 8 + rq) * 128 +
                               (matq & 1) * 16);

    const int nch = K >> 6;
    load_chunk(0, sb);

    for (int ch = 0; ch < nch; ++ch) {
        const uint32_t stg = sb + (uint32_t)(ch & 1) * STG_SZ;
        if (ch + 1 < nch) {
            load_chunk((ch + 1) << 6, sb + (uint32_t)((ch + 1) & 1) * STG_SZ);
            CP_WAIT(1);
        } else {
            CP_WAIT(0);
        }
        __syncthreads();

#pragma unroll
        for (int ks = 0; ks < 4; ++ks) {
            uint32_t ah[4][4], al[4][4], bh[2][4], bl[2][4];
#pragma unroll
            for (int mt = 0; mt < 4; ++mt) {
                const uint32_t off = swz128(aRowB[mt] + ks * 32);
                LDMX4(ah[mt][0], ah[mt][1], ah[mt][2], ah[mt][3],
                      stg + T_AH + off);
                LDMX4(al[mt][0], al[mt][1], al[mt][2], al[mt][3],
                      stg + T_AL + off);
            }
#pragma unroll
            for (int nt = 0; nt < 2; ++nt) {
                const uint32_t off = swz128(bRowB[nt] + ks * 32);
                LDMX4(bh[nt][0], bh[nt][1], bh[nt][2], bh[nt][3],
                      stg + T_BH + off);
                LDMX4(bl[nt][0], bl[nt][1], bl[nt][2], bl[nt][3],
                      stg + T_BL + off);
            }
#pragma unroll
            for (int mt = 0; mt < 4; ++mt) {
#pragma unroll
                for (int nt = 0; nt < 2; ++nt) {
#pragma unroll
                    for (int h = 0; h < 2; ++h) {
                        const int j = nt * 2 + h;
                        MMA16816(acc[mt][j], ah[mt], bh[nt][2 * h], bh[nt][2 * h + 1]);
                        MMA16816(acc[mt][j], ah[mt], bl[nt][2 * h], bl[nt][2 * h + 1]);
                        MMA16816(acc[mt][j], al[mt], bh[nt][2 * h], bh[nt][2 * h + 1]);
                    }
                }
            }
        }
        __syncthreads();
    }

    const int rbase = r0 + wm + (lane >> 2);
    const int cbase = c0 + wn + (lane & 3) * 2;
#pragma unroll
    for (int j = 0; j < 4; ++j) {
        const int col = cbase + j * 8;
        const float bx = __ldg(&bias[col]);
        const float by = __ldg(&bias[col + 1]);
#pragma unroll
        for (int mt = 0; mt < 4; ++mt) {
            const int row = rbase + mt * 16;
            float2 v0 = make_float2(acc[mt][j][0] + bx, acc[mt][j][1] + by);
            float2 v1 = make_float2(acc[mt][j][2] + bx, acc[mt][j][3] + by);
            *reinterpret_cast<float2*>(&Cmat[(size_t)row * Nc + col]) = v0;
            *reinterpret_cast<float2*>(&Cmat[(size_t)(row + 8) * Nc + col]) = v1;
        }
    }
}

// ===========================================================================
// Fused softmax + loc + deformable sampling + mid bf16-split epilogue.
// ===========================================================================
__global__ __launch_bounds__(256)
void deform_fused(const float* __restrict__ val,
                  const float* __restrict__ offattn,
                  const float* __restrict__ refpts,
                  float* __restrict__ loc_out,
                  float* __restrict__ attn_out,
                  __nv_bfloat16* __restrict__ mid_h,
                  __nv_bfloat16* __restrict__ mid_l)
{
    const int wid = threadIdx.x >> 5;
    const int lane = threadIdx.x & 31;
    const long long gw = (long long)blockIdx.x * 8 + wid;
    const int m = (int)(gw & 7);
    const int row = (int)(gw >> 3);
    const int n = row >> 11;
    const int sg = lane >> 3;       // sample slot 0..3
    const int cg = lane & 7;        // float4 channel group

    // --- softmax over 16 logits + loc ---
    const int oroW = row * 256 + m * 16;
    float logit[4], offv[4];
#pragma unroll
    for (int g = 0; g < 4; ++g) {
        const int i = g * 4 + sg;
        offv[g]  = __ldg(&offattn[oroW + i]);
        logit[g] = __ldg(&offattn[oroW + 128 + i]);
    }
    float mx = fmaxf(fmaxf(logit[0], logit[1]), fmaxf(logit[2], logit[3]));
    mx = fmaxf(mx, __shfl_xor_sync(0xffffffffu, mx, 8));
    mx = fmaxf(mx, __shfl_xor_sync(0xffffffffu, mx, 16));
    float e[4], s = 0.f;
#pragma unroll
    for (int g = 0; g < 4; ++g) { e[g] = __expf(logit[g] - mx); s += e[g]; }
    s += __shfl_xor_sync(0xffffffffu, s, 8);
    s += __shfl_xor_sync(0xffffffffu, s, 16);

    float aw[4], lc[4];
#pragma unroll
    for (int g = 0; g < 4; ++g) {
        aw[g] = e[g] / s;
        lc[g] = __ldg(&refpts[row * LL + g]) + offv[g] / (float)c_lens[g];
    }
    if (cg == 0) {
        const int ob = row * MLP + m * 16;
#pragma unroll
        for (int g = 0; g < 4; ++g) {
            attn_out[ob + g * 4 + sg] = aw[g];
            loc_out[ob + g * 4 + sg]  = lc[g];
        }
    }

    // --- sampling ---
    const float4* vb = reinterpret_cast<const float4*>(
        val + ((size_t)n * SS) * CC + m * DH) + cg;

    float4 acc = make_float4(0.f, 0.f, 0.f, 0.f);
#pragma unroll
    for (int g = 0; g < 4; ++g) {           // level == g
        const int T = c_lens[g];
        const int st = c_start[g];
        const float pos = lc[g] * (float)T - 0.5f;
        const float x0f = floorf(pos);
        const float fr = pos - x0f;
        const int x0 = (int)x0f;

        const float w0 = (x0 >= 0 && x0 < T) ? (1.f - fr) * aw[g] : 0.f;
        const float w1 = (x0 + 1 >= 0 && x0 + 1 < T) ? fr * aw[g] : 0.f;
        const int i0 = min(max(x0, 0), T - 1);
        const int i1 = min(max(x0 + 1, 0), T - 1);
        if (w0 != 0.f) {
            const float4 v = vb[(size_t)(st + i0) * (CC / 4)];
            acc.x += w0 * v.x; acc.y += w0 * v.y;
            acc.z += w0 * v.z; acc.w += w0 * v.w;
        }
        if (w1 != 0.f) {
            const float4 v = vb[(size_t)(st + i1) * (CC / 4)];
            acc.x += w1 * v.x; acc.y += w1 * v.y;
            acc.z += w1 * v.z; acc.w += w1 * v.w;
        }
    }
#pragma unroll
    for (int o = 8; o <= 16; o <<= 1) {
        acc.x += __shfl_xor_sync(0xffffffffu, acc.x, o);
        acc.y += __shfl_xor_sync(0xffffffffu, acc.y, o);
        acc.z += __shfl_xor_sync(0xffffffffu, acc.z, o);
        acc.w += __shfl_xor_sync(0xffffffffu, acc.w, o);
    }
    if (sg == 0) {
        float l0, l1, l2, l3;
        const uint32_t h01 = pack_hi(acc.x, acc.y, l0, l1);
        const uint32_t h23 = pack_hi(acc.z, acc.w, l2, l3);
        const size_t base = (size_t)row * CC + m * DH + cg * 4;
        *reinterpret_cast<uint2*>(&mid_h[base]) = make_uint2(h01, h23);
        *reinterpret_cast<uint2*>(&mid_l[base]) =
            make_uint2(pack_bf(l0, l1), pack_bf(l2, l3));
    }
}

// ---------------------------------------------------------------------------
extern "C" void kernel_launch(void* const* d_in, const int* in_sizes, int n_in,
                              void* d_out, int out_size)
{
    const float* query   = (const float*)d_in[0];
    const float* refpts  = (const float*)d_in[1];
    const float* in_flat = (const float*)d_in[2];
    const float* W_off   = (const float*)d_in[5];
    const float* b_off   = (const float*)d_in[6];
    const float* W_attn  = (const float*)d_in[7];
    const float* b_attn  = (const float*)d_in[8];
    const float* W_val   = (const float*)d_in[9];
    const float* b_val   = (const float*)d_in[10];
    const float* W_out   = (const float*)d_in[11];
    const float* b_out   = (const float*)d_in[12];

    float* out_main = (float*)d_out;
    float* out_loc  = out_main + (size_t)ROWS_Q * CC;
    float* out_attn = out_loc  + (size_t)ROWS_Q * MLP;

    float *d_val, *d_offattn, *d_bcat;
    __nv_bfloat16 *d_in_h, *d_in_l, *d_q_h, *d_q_l, *d_mid_h, *d_mid_l;
    __nv_bfloat16 *d_wv_h, *d_wv_l, *d_wcat_h, *d_wcat_l, *d_wo_h, *d_wo_l;
    cudaGetSymbolAddress((void**)&d_val,     g_val);
    cudaGetSymbolAddress((void**)&d_offattn, g_offattn);
    cudaGetSymbolAddress((void**)&d_bcat,    g_bcat);
    cudaGetSymbolAddress((void**)&d_in_h,    g_in_h);
    cudaGetSymbolAddress((void**)&d_in_l,    g_in_l);
    cudaGetSymbolAddress((void**)&d_q_h,     g_q_h);
    cudaGetSymbolAddress((void**)&d_q_l,     g_q_l);
    cudaGetSymbolAddress((void**)&d_mid_h,   g_mid_h);
    cudaGetSymbolAddress((void**)&d_mid_l,   g_mid_l);
    cudaGetSymbolAddress((void**)&d_wv_h,    g_wv_h);
    cudaGetSymbolAddress((void**)&d_wv_l,    g_wv_l);
    cudaGetSymbolAddress((void**)&d_wcat_h,  g_wcat_h);
    cudaGetSymbolAddress((void**)&d_wcat_l,  g_wcat_l);
    cudaGetSymbolAddress((void**)&d_wo_h,    g_wo_h);
    cudaGetSymbolAddress((void**)&d_wo_l,    g_wo_l);

    static bool init_done = false;
    static cudaStream_t s2;
    static cudaEvent_t evFork, evW, ev1;
    if (!init_done) {
        cudaFuncSetAttribute(gemm_bf16v2,
                             cudaFuncAttributeMaxDynamicSharedMemorySize,
                             GEMM_SMEM);
        cudaStreamCreateWithFlags(&s2, cudaStreamNonBlocking);
        cudaEventCreateWithFlags(&evFork, cudaEventDisableTiming);
        cudaEventCreateWithFlags(&evW,    cudaEventDisableTiming);
        cudaEventCreateWithFlags(&ev1,    cudaEventDisableTiming);
        init_done = true;
    }

    // ---- fork: side stream s2 handles the value branch ----
    cudaEventRecord(evFork, 0);
    cudaStreamWaitEvent(s2, evFork, 0);

    // s2: convert in_flatten (heavy, 24us)
    convert_act<<<1536, 256, 0, s2>>>(in_flat, d_in_h, d_in_l, ROWS_V * CC / 4);

    // default: weights + query conversion, then offattn GEMM
    convert_wts_all<<<48, 256>>>(W_val, W_off, W_attn, W_out,
                                 d_wv_h, d_wv_l, d_wcat_h, d_wcat_l,
                                 d_wo_h, d_wo_l, b_off, b_attn, d_bcat);
    cudaEventRecord(evW, 0);   // weights (incl. W_val) ready
    convert_act<<<512, 256>>>(query, d_q_h, d_q_l, ROWS_Q * CC / 4);
    gemm_bf16v2<<<dim3(2, ROWS_Q / 128), 256, GEMM_SMEM>>>(
        d_q_h, d_q_l, d_wcat_h, d_wcat_l, d_bcat, d_offattn, ROWS_Q, 256, CC);

    // s2: value projection (needs in_h/in_l + W_val which is behind evW)
    cudaStreamWaitEvent(s2, evW, 0);
    gemm_bf16v2<<<dim3(2, ROWS_V / 128), 256, GEMM_SMEM, s2>>>(
        d_in_h, d_in_l, d_wv_h, d_wv_l, b_val, d_val, ROWS_V, CC, CC);
    cudaEventRecord(ev1, s2);

    // ---- join, then fused deform + output projection on default ----
    cudaStreamWaitEvent(0, ev1, 0);
    deform_fused<<<ROWS_Q, 256>>>(d_val, d_offattn, refpts,
                                  out_loc, out_attn, d_mid_h, d_mid_l);
    gemm_bf16v2<<<dim3(2, ROWS_Q / 128), 256, GEMM_SMEM>>>(
        d_mid_h, d_mid_l, d_wo_h, d_wo_l, b_out, out_main, ROWS_Q, CC, CC);
}